// round 1
// baseline (speedup 1.0000x reference)
#include <cuda_runtime.h>
#include <math.h>

#define BB 512
#define SS 256
#define NUM_LOC 50000
#define NUM_USERS 10000
#define DD 256
#define NG 1024        // 4*D gate dim (gate-interleaved n' = 4*cell + gate)
#define NEGV -1000000000.0f

// ---------------- device scratch (no cudaMalloc allowed) ----------------
__device__ float g_locC[(size_t)NUM_LOC * NG];     // 204.8 MB
__device__ float g_userC[(size_t)NUM_USERS * NG];  // 41 MB
__device__ float g_hourC[25 * NG];
__device__ float g_wdC[8 * NG];
__device__ float g_biasr[NG];
__device__ float g_Whhr[NG * DD];                  // gate-interleaved W_hh
__device__ float g_h[2][BB * DD];                  // double-buffered hidden
__device__ float g_c[BB * DD];
__device__ float g_context[BB * DD];
__device__ int   g_seqlen[BB];
__device__ float g_hidden1[BB * DD];
__device__ float g_mix[BB];
__device__ int   g_recloc[BB * 5];
__device__ float g_recscore[BB * 5];
__device__ int   g_maskflag[1];

__device__ __forceinline__ float geluf(float x) {
    return 0.5f * x * (1.0f + erff(x * 0.70710678118654752f));
}
__device__ __forceinline__ float sigm(float x) { return 1.0f / (1.0f + expf(-x)); }

// ---------------- mask dtype detection ----------------
// mask = (arange(S) < length), prefix of ones per row. If stored as 1-byte,
// many bytes at offset ≡ 1 (mod 4) are 1; if 4-byte (int32/float32), those
// bytes are always 0.
__global__ void detect_mask(const unsigned char* mask) {
    __shared__ int s;
    if (threadIdx.x == 0) s = 0;
    __syncthreads();
    int f = 0;
    for (int i = threadIdx.x * 4 + 1; i < BB * SS; i += blockDim.x * 4)
        if (mask[i]) f = 1;
    if (f) atomicOr(&s, 1);
    __syncthreads();
    if (threadIdx.x == 0) g_maskflag[0] = s;
}

__global__ void seqlen_kernel(const void* mask) {
    int b = blockIdx.x * blockDim.x + threadIdx.x;
    if (b >= BB) return;
    int flag = g_maskflag[0];
    int cnt = 0;
    if (flag) {
        const unsigned char* m = (const unsigned char*)mask;
        for (int s = 0; s < SS; s++) cnt += (m[b * SS + s] != 0);
    } else {
        const int* m = (const int*)mask;
        for (int s = 0; s < SS; s++) cnt += (m[b * SS + s] != 0);
    }
    g_seqlen[b] = cnt - 1;
}

__global__ void zero_state() {
    int i = blockIdx.x * 256 + threadIdx.x;   // grid 512 -> 131072 exact
    g_h[0][i] = 0.0f;
    g_c[i] = 0.0f;
}

// gate-interleave W_hh and biases: n' = 4*d + g  <->  row = g*256 + d
__global__ void reorder_kernel(const float* __restrict__ W_hh,
                               const float* __restrict__ b_ih,
                               const float* __restrict__ b_hh) {
    int np = blockIdx.x;                     // 0..1023
    int row = ((np & 3) << 8) + (np >> 2);
    g_Whhr[np * DD + threadIdx.x] = W_hh[row * DD + threadIdx.x];
    if (threadIdx.x == 0) g_biasr[np] = b_ih[row] + b_hh[row];
}

// ---------------- contribution GEMM: C[m, n'] = sum_k A[m,k] * W_ih[row(n'), k0+k]
// Tile: BM=128, BN=64, BK=16, 256 threads, thread tile 8x4.
__global__ void contrib_gemm(const float* __restrict__ A, int M, int lda,
                             int k0, int K, const float* __restrict__ Wih,
                             int which) {
    float* C = (which == 0) ? g_locC : (which == 1) ? g_userC
             : (which == 2) ? g_hourC : g_wdC;
    __shared__ float As[128 * 20];
    __shared__ float Ws[16 * 68];
    const int m0 = blockIdx.x * 128;
    const int n0 = blockIdx.y * 64;
    const int tid = threadIdx.x;
    const int ty = tid >> 4, tx = tid & 15;

    float acc[8][4];
#pragma unroll
    for (int i = 0; i < 8; i++)
#pragma unroll
        for (int j = 0; j < 4; j++) acc[i][j] = 0.0f;

    const int a_mi = tid >> 1;
    const int a_kq = (tid & 1) * 8;
    const int w_n = tid >> 2;
    const int w_kq = (tid & 3) * 4;
    const int nn = n0 + w_n;
    const int wr = ((nn & 3) << 8) + (nn >> 2);

    for (int kidx = 0; kidx < K; kidx += 16) {
        // load A tile (zero-fill OOB rows)
        float4 av0, av1;
        int row = m0 + a_mi;
        if (row < M) {
            const float* ap = A + (size_t)row * lda + kidx + a_kq;
            av0 = *(const float4*)ap;
            av1 = *(const float4*)(ap + 4);
        } else {
            av0 = make_float4(0.f, 0.f, 0.f, 0.f);
            av1 = av0;
        }
        *(float4*)&As[a_mi * 20 + a_kq] = av0;
        *(float4*)&As[a_mi * 20 + a_kq + 4] = av1;

        // load W tile transposed into Ws[k][n]
        const float* wp = Wih + (size_t)wr * 448 + k0 + kidx + w_kq;
        float4 wv = *(const float4*)wp;
        Ws[(w_kq + 0) * 68 + w_n] = wv.x;
        Ws[(w_kq + 1) * 68 + w_n] = wv.y;
        Ws[(w_kq + 2) * 68 + w_n] = wv.z;
        Ws[(w_kq + 3) * 68 + w_n] = wv.w;
        __syncthreads();

#pragma unroll
        for (int k = 0; k < 16; k++) {
            float a[8];
#pragma unroll
            for (int i = 0; i < 8; i++) a[i] = As[(ty * 8 + i) * 20 + k];
            float4 w = *(const float4*)&Ws[k * 68 + tx * 4];
#pragma unroll
            for (int i = 0; i < 8; i++) {
                acc[i][0] += a[i] * w.x;
                acc[i][1] += a[i] * w.y;
                acc[i][2] += a[i] * w.z;
                acc[i][3] += a[i] * w.w;
            }
        }
        __syncthreads();
    }
#pragma unroll
    for (int i = 0; i < 8; i++) {
        int row = m0 + ty * 8 + i;
        if (row < M) {
            float4 v = make_float4(acc[i][0], acc[i][1], acc[i][2], acc[i][3]);
            *(float4*)&C[(size_t)row * NG + n0 + tx * 4] = v;
        }
    }
}

// ---------------- fused LSTM step: gather contribs + h@Whh^T + pointwise ----
// grid (16, 8), 256 threads. Tile: 32 batch rows x 32 cells (=128 gate cols).
__global__ void lstm_step(const int* __restrict__ locs, const int* __restrict__ usrs,
                          const int* __restrict__ wds, const int* __restrict__ sms,
                          int t) {
    const int tid = threadIdx.x;
    const int cell = tid & 31;
    const int bG = tid >> 5;            // 0..7, owns 4 batch rows
    const int b0 = blockIdx.x * 32;
    const int n0 = blockIdx.y * 128;
    const float* __restrict__ h_in = g_h[t & 1];
    float* __restrict__ h_out = g_h[(t + 1) & 1];

    __shared__ float hs[32 * 33];
    __shared__ float ws[32 * 132];

    const int col = n0 + cell * 4;
    float4 acc[4];
#pragma unroll
    for (int j = 0; j < 4; j++) {
        int b = b0 + bG * 4 + j;
        int li = locs[b * SS + t];
        int ui = usrs[b * SS + t];
        int wi = wds[b * SS + t];
        int sm = sms[b * SS + t];
        int hr = sm / 60;
        float4 v = *(const float4*)&g_biasr[col];
        float4 a1 = *(const float4*)&g_locC[(size_t)li * NG + col];
        float4 a2 = *(const float4*)&g_userC[(size_t)ui * NG + col];
        float4 a3 = *(const float4*)&g_hourC[hr * NG + col];
        float4 a4 = *(const float4*)&g_wdC[wi * NG + col];
        acc[j].x = v.x + a1.x + a2.x + a3.x + a4.x;
        acc[j].y = v.y + a1.y + a2.y + a3.y + a4.y;
        acc[j].z = v.z + a1.z + a2.z + a3.z + a4.z;
        acc[j].w = v.w + a1.w + a2.w + a3.w + a4.w;
    }

    const int h_bi = tid >> 3;
    const int h_kq = (tid & 7) * 4;
    const int w_n = tid >> 1;
    const int w_kq = (tid & 1) * 16;

    for (int kk0 = 0; kk0 < DD; kk0 += 32) {
        float4 hv = *(const float4*)&h_in[(b0 + h_bi) * DD + kk0 + h_kq];
        hs[(h_kq + 0) * 33 + h_bi] = hv.x;
        hs[(h_kq + 1) * 33 + h_bi] = hv.y;
        hs[(h_kq + 2) * 33 + h_bi] = hv.z;
        hs[(h_kq + 3) * 33 + h_bi] = hv.w;

        const float* wp = &g_Whhr[(n0 + w_n) * DD + kk0 + w_kq];
#pragma unroll
        for (int q = 0; q < 4; q++) {
            float4 wv = *(const float4*)(wp + q * 4);
            int kr = w_kq + q * 4;
            ws[(kr + 0) * 132 + w_n] = wv.x;
            ws[(kr + 1) * 132 + w_n] = wv.y;
            ws[(kr + 2) * 132 + w_n] = wv.z;
            ws[(kr + 3) * 132 + w_n] = wv.w;
        }
        __syncthreads();

#pragma unroll
        for (int k = 0; k < 32; k++) {
            float4 w4 = *(const float4*)&ws[k * 132 + cell * 4];
#pragma unroll
            for (int j = 0; j < 4; j++) {
                float hb = hs[k * 33 + bG * 4 + j];
                acc[j].x += hb * w4.x;
                acc[j].y += hb * w4.y;
                acc[j].z += hb * w4.z;
                acc[j].w += hb * w4.w;
            }
        }
        __syncthreads();
    }

    const int cellG = blockIdx.y * 32 + cell;
#pragma unroll
    for (int j = 0; j < 4; j++) {
        int b = b0 + bG * 4 + j;
        float ii = acc[j].x, ff = acc[j].y, gg = acc[j].z, oo = acc[j].w;
        float cold = g_c[b * DD + cellG];
        float cn = sigm(ff) * cold + sigm(ii) * tanhf(gg);
        float hn = sigm(oo) * tanhf(cn);
        g_c[b * DD + cellG] = cn;
        h_out[b * DD + cellG] = hn;
        if (t == g_seqlen[b]) g_context[b * DD + cellG] = hn;
    }
}

// ---------------- context MLP: hidden1 = gelu(ctx @ np_W1^T + b1); mix ------
__global__ void ctx_mlp(const float* __restrict__ np_W1, const float* __restrict__ np_b1,
                        const float* __restrict__ mx_W, const float* __restrict__ mx_b) {
    int b = blockIdx.x, tid = threadIdx.x;
    __shared__ float ctx[DD];
    __shared__ float red[DD];
    ctx[tid] = g_context[b * DD + tid];
    __syncthreads();
    float accv = np_b1[tid];
    const float* w = np_W1 + (size_t)tid * DD;
#pragma unroll 4
    for (int k = 0; k < DD; k++) accv += ctx[k] * w[k];
    g_hidden1[b * DD + tid] = geluf(accv);

    red[tid] = ctx[tid] * mx_W[tid];
    __syncthreads();
    for (int off = 128; off > 0; off >>= 1) {
        if (tid < off) red[tid] += red[tid + off];
        __syncthreads();
    }
    if (tid == 0) g_mix[b] = sigm(red[0] + mx_b[0]) * 0.9f + 0.05f;
}

// ---------------- recent-location scoring + dedup ----------------
__global__ void recent_kernel(const int* __restrict__ locations,
                              const int* __restrict__ start_mins,
                              const float* __restrict__ loc_table,
                              const float* __restrict__ sc_W1,
                              const float* __restrict__ sc_b1,
                              const float* __restrict__ sc_W2,
                              const float* __restrict__ sc_b2) {
    int b = blockIdx.x, tid = threadIdx.x;   // 128 threads
    __shared__ int rloc[5];
    __shared__ float td[5];
    __shared__ int val[5];
    __shared__ float hid[5][128];
    if (tid < 5) {
        int sl = g_seqlen[b];
        int idx = sl - tid;
        val[tid] = (idx >= 0);
        int ic = idx < 0 ? 0 : idx;
        rloc[tid] = locations[b * SS + ic];
        int ct = start_mins[b * SS + sl];
        td[tid] = (float)(ct - start_mins[b * SS + ic]) / 1440.0f;
    }
    __syncthreads();
    for (int j = 0; j < 5; j++) {
        const float* lt = loc_table + (size_t)rloc[j] * DD;
        const float* w = sc_W1 + (size_t)tid * 258;
        float a = sc_b1[tid] + td[j] * w[256] + (float)j * w[257];
#pragma unroll 4
        for (int k = 0; k < DD; k++) a += lt[k] * w[k];
        hid[j][tid] = geluf(a);
    }
    __syncthreads();
    if (tid < 5) {
        float sc = sc_b2[0];
        for (int k = 0; k < 128; k++) sc += hid[tid][k] * sc_W2[k];
        int keep = val[tid];
        for (int jp = 0; jp < tid; jp++)
            if (val[jp] && rloc[jp] == rloc[tid]) keep = 0;
        g_recloc[b * 5 + tid] = keep ? rloc[tid] : -1;
        g_recscore[b * 5 + tid] = sc;
    }
}

// ---------------- vocab GEMM with blend epilogue ----------------
// out[b,l] = mix[b]*NEG + (1-mix[b]) * (hidden1[b] . np_W2[l] + np_b2[l])
__global__ void newlogits_gemm(const float* __restrict__ np_W2,
                               const float* __restrict__ np_b2,
                               float* __restrict__ out) {
    __shared__ float As[128 * 20];
    __shared__ float Ws[16 * 68];
    const int m0 = blockIdx.x * 128;
    const int n0 = blockIdx.y * 64;
    const int tid = threadIdx.x;
    const int ty = tid >> 4, tx = tid & 15;

    float acc[8][4];
#pragma unroll
    for (int i = 0; i < 8; i++)
#pragma unroll
        for (int j = 0; j < 4; j++) acc[i][j] = 0.0f;

    const int a_mi = tid >> 1;
    const int a_kq = (tid & 1) * 8;
    const int w_n = tid >> 2;
    const int w_kq = (tid & 3) * 4;
    const int wrow = n0 + w_n;

    for (int kidx = 0; kidx < DD; kidx += 16) {
        const float* ap = g_hidden1 + (size_t)(m0 + a_mi) * DD + kidx + a_kq;
        float4 av0 = *(const float4*)ap;
        float4 av1 = *(const float4*)(ap + 4);
        *(float4*)&As[a_mi * 20 + a_kq] = av0;
        *(float4*)&As[a_mi * 20 + a_kq + 4] = av1;

        float4 wv;
        if (wrow < NUM_LOC) {
            wv = *(const float4*)(np_W2 + (size_t)wrow * DD + kidx + w_kq);
        } else {
            wv = make_float4(0.f, 0.f, 0.f, 0.f);
        }
        Ws[(w_kq + 0) * 68 + w_n] = wv.x;
        Ws[(w_kq + 1) * 68 + w_n] = wv.y;
        Ws[(w_kq + 2) * 68 + w_n] = wv.z;
        Ws[(w_kq + 3) * 68 + w_n] = wv.w;
        __syncthreads();

#pragma unroll
        for (int k = 0; k < 16; k++) {
            float a[8];
#pragma unroll
            for (int i = 0; i < 8; i++) a[i] = As[(ty * 8 + i) * 20 + k];
            float4 w = *(const float4*)&Ws[k * 68 + tx * 4];
#pragma unroll
            for (int i = 0; i < 8; i++) {
                acc[i][0] += a[i] * w.x;
                acc[i][1] += a[i] * w.y;
                acc[i][2] += a[i] * w.z;
                acc[i][3] += a[i] * w.w;
            }
        }
        __syncthreads();
    }

    const int coln = n0 + tx * 4;
    if (coln < NUM_LOC) {
        float4 b2 = *(const float4*)&np_b2[coln];
#pragma unroll
        for (int i = 0; i < 8; i++) {
            int row = m0 + ty * 8 + i;
            float mm = g_mix[row];
            float om = 1.0f - mm;
            float base = mm * NEGV;
            float4 v;
            v.x = base + om * (acc[i][0] + b2.x);
            v.y = base + om * (acc[i][1] + b2.y);
            v.z = base + om * (acc[i][2] + b2.z);
            v.w = base + om * (acc[i][3] + b2.w);
            *(float4*)&out[(size_t)row * NUM_LOC + coln] = v;
        }
    }
}

// ---------------- fixup: overwrite kept recent locations ----------------
__global__ void fixup_kernel(const float* __restrict__ np_W2,
                             const float* __restrict__ np_b2,
                             float* __restrict__ out) {
    int b = blockIdx.x, tid = threadIdx.x;   // 256 threads
    __shared__ float h1[DD];
    __shared__ float red[DD];
    h1[tid] = g_hidden1[b * DD + tid];
    __syncthreads();
    float mm = g_mix[b];
    for (int j = 0; j < 5; j++) {
        int l = g_recloc[b * 5 + j];         // uniform across block
        if (l < 0) continue;
        red[tid] = h1[tid] * np_W2[(size_t)l * DD + tid];
        __syncthreads();
        for (int off = 128; off > 0; off >>= 1) {
            if (tid < off) red[tid] += red[tid + off];
            __syncthreads();
        }
        if (tid == 0)
            out[(size_t)b * NUM_LOC + l] =
                mm * g_recscore[b * 5 + j] + (1.0f - mm) * (red[0] + np_b2[l]);
        __syncthreads();
    }
}

// ---------------- launch ----------------
extern "C" void kernel_launch(void* const* d_in, const int* in_sizes, int n_in,
                              void* d_out, int out_size) {
    const int* locations   = (const int*)d_in[0];
    const int* users       = (const int*)d_in[1];
    const int* weekdays    = (const int*)d_in[2];
    const int* start_mins  = (const int*)d_in[3];
    const void* mask       = d_in[4];
    const float* loc_table  = (const float*)d_in[5];
    const float* user_table = (const float*)d_in[6];
    const float* hour_table = (const float*)d_in[7];
    const float* wd_table   = (const float*)d_in[8];
    const float* W_ih = (const float*)d_in[9];
    const float* W_hh = (const float*)d_in[10];
    const float* b_ih = (const float*)d_in[11];
    const float* b_hh = (const float*)d_in[12];
    const float* sc_W1 = (const float*)d_in[13];
    const float* sc_b1 = (const float*)d_in[14];
    const float* sc_W2 = (const float*)d_in[15];
    const float* sc_b2 = (const float*)d_in[16];
    const float* np_W1 = (const float*)d_in[17];
    const float* np_b1 = (const float*)d_in[18];
    const float* np_W2 = (const float*)d_in[19];
    const float* np_b2 = (const float*)d_in[20];
    const float* mx_W = (const float*)d_in[21];
    const float* mx_b = (const float*)d_in[22];
    float* out = (float*)d_out;

    detect_mask<<<1, 256>>>((const unsigned char*)mask);
    seqlen_kernel<<<2, 256>>>(mask);
    zero_state<<<512, 256>>>();
    reorder_kernel<<<1024, 256>>>(W_hh, b_ih, b_hh);

    contrib_gemm<<<dim3(391, 16), 256>>>(loc_table, NUM_LOC, 256, 0, 256, W_ih, 0);
    contrib_gemm<<<dim3(79, 16), 256>>>(user_table, NUM_USERS, 64, 256, 64, W_ih, 1);
    contrib_gemm<<<dim3(1, 16), 256>>>(hour_table, 25, 64, 320, 64, W_ih, 2);
    contrib_gemm<<<dim3(1, 16), 256>>>(wd_table, 8, 64, 384, 64, W_ih, 3);

    for (int t = 0; t < SS; t++)
        lstm_step<<<dim3(16, 8), 256>>>(locations, users, weekdays, start_mins, t);

    ctx_mlp<<<512, 256>>>(np_W1, np_b1, mx_W, mx_b);
    recent_kernel<<<512, 128>>>(locations, start_mins, loc_table,
                                sc_W1, sc_b1, sc_W2, sc_b2);
    newlogits_gemm<<<dim3(4, 782), 256>>>(np_W2, np_b2, out);
    fixup_kernel<<<512, 256>>>(np_W2, np_b2, out);
}

// round 2
// speedup vs baseline: 1.4391x; 1.4391x over previous
#include <cuda_runtime.h>
#include <math.h>

#define BB 512
#define SS 256
#define NUM_LOC 50000
#define NUM_USERS 10000
#define DD 256
#define NG 1024        // 4*D gate dim (gate-interleaved n' = 4*cell + gate)
#define NEGV -1000000000.0f

// ---------------- device scratch (no cudaMalloc allowed) ----------------
__device__ float g_locC[(size_t)NUM_LOC * NG];     // 204.8 MB (bias folded in)
__device__ float g_userC[(size_t)NUM_USERS * NG];  // 41 MB
__device__ float g_hourC[25 * NG];
__device__ float g_wdC[8 * NG];
__device__ float g_biasr[NG];
__device__ float g_Whhr[NG * DD];                  // gate-interleaved W_hh
__device__ float g_h[2][BB * DD];                  // double-buffered hidden
__device__ float g_context[BB * DD];
__device__ int   g_seqlen[BB];
__device__ float g_hidden1[BB * DD];
__device__ float g_mix[BB];
__device__ int   g_recloc[BB * 5];
__device__ float g_recscore[BB * 5];
__device__ int   g_maskflag[1];
__device__ int   g_bar[SS * 16];                   // per-step, per-batch-group arrive counters

typedef unsigned long long ull;
__device__ __forceinline__ void fma2(ull &d, ull a, ull b) {
    asm("fma.rn.f32x2 %0, %1, %2, %0;" : "+l"(d) : "l"(a), "l"(b));
}
__device__ __forceinline__ ull pk2(float x, float y) {
    ull r; asm("mov.b64 %0, {%1, %2};" : "=l"(r) : "f"(x), "f"(y)); return r;
}
__device__ __forceinline__ float2 upk(ull v) {
    float2 r; asm("mov.b64 {%0, %1}, %2;" : "=f"(r.x), "=f"(r.y) : "l"(v)); return r;
}

__device__ __forceinline__ float geluf(float x) {
    return 0.5f * x * (1.0f + erff(x * 0.70710678118654752f));
}
__device__ __forceinline__ float sigm(float x) { return 1.0f / (1.0f + __expf(-x)); }
__device__ __forceinline__ float tanh_(float x) {
    return 1.0f - 2.0f / (__expf(2.0f * x) + 1.0f);
}

// ---------------- mask dtype detection ----------------
__global__ void detect_mask(const unsigned char* mask) {
    __shared__ int s;
    if (threadIdx.x == 0) s = 0;
    __syncthreads();
    int f = 0;
    for (int i = threadIdx.x * 4 + 1; i < BB * SS; i += blockDim.x * 4)
        if (mask[i]) f = 1;
    if (f) atomicOr(&s, 1);
    __syncthreads();
    if (threadIdx.x == 0) g_maskflag[0] = s;
}

__global__ void seqlen_kernel(const void* mask) {
    int b = blockIdx.x * blockDim.x + threadIdx.x;
    if (b >= BB) return;
    int flag = g_maskflag[0];
    int cnt = 0;
    if (flag) {
        const unsigned char* m = (const unsigned char*)mask;
        for (int s = 0; s < SS; s++) cnt += (m[b * SS + s] != 0);
    } else {
        const int* m = (const int*)mask;
        for (int s = 0; s < SS; s++) cnt += (m[b * SS + s] != 0);
    }
    g_seqlen[b] = cnt - 1;
}

// gate-interleave W_hh and biases; also zero barrier counters
__global__ void reorder_kernel(const float* __restrict__ W_hh,
                               const float* __restrict__ b_ih,
                               const float* __restrict__ b_hh) {
    int np = blockIdx.x;                     // 0..1023
    int row = ((np & 3) << 8) + (np >> 2);
    g_Whhr[np * DD + threadIdx.x] = W_hh[row * DD + threadIdx.x];
    if (threadIdx.x == 0) g_biasr[np] = b_ih[row] + b_hh[row];
    if (np < 16) g_bar[np * 256 + threadIdx.x] = 0;
}

// ---------------- 128x128x8 double-buffered fp32x2 GEMM ----------------
// C[m,n] = sum_k A[m,k] * W[rowmap(n), k0+k]
// mode 0..3: contrib tables (interleaved rowmap into W_ih; mode 0 adds bias)
// mode 4:    vocab logits with blend epilogue (A = g_hidden1, W = np_W2)
__global__ void __launch_bounds__(256)
gemm128(const float* __restrict__ A, int M, int lda,
        const float* __restrict__ W, int ldw, int k0, int K,
        int N, int mode, const float* __restrict__ bias2,
        float* __restrict__ out) {
    __shared__ float As[2][8][132];
    __shared__ float Ws[2][8][132];
    if (mode == 4) A = g_hidden1;

    const int m0 = blockIdx.x * 128;
    const int n0 = blockIdx.y * 128;
    const int tid = threadIdx.x;
    const int tx = tid & 15, ty = tid >> 4;

    const int lr = tid >> 1;            // 0..127 tile row/col for staging
    const int lk = (tid & 1) * 4;       // k quad

    const bool aok = (m0 + lr) < M;
    const float* ap = A + (size_t)(aok ? (m0 + lr) : 0) * lda + lk;
    int wn = n0 + lr;
    bool wok;
    const float* wp;
    if (mode < 4) {
        int wr = ((wn & 3) << 8) + (wn >> 2);
        wp = W + (size_t)wr * ldw + k0 + lk;
        wok = true;
    } else {
        wok = wn < N;
        wp = W + (size_t)(wok ? wn : 0) * ldw + lk;
    }

    ull acc[8][4];
#pragma unroll
    for (int r = 0; r < 8; r++)
#pragma unroll
        for (int p = 0; p < 4; p++) acc[r][p] = 0ULL;

    const float4 Z = make_float4(0.f, 0.f, 0.f, 0.f);
    const int nk = K >> 3;

    float4 va = aok ? *(const float4*)ap : Z;
    float4 vw = wok ? *(const float4*)wp : Z;
    As[0][lk + 0][lr] = va.x; As[0][lk + 1][lr] = va.y;
    As[0][lk + 2][lr] = va.z; As[0][lk + 3][lr] = va.w;
    Ws[0][lk + 0][lr] = vw.x; Ws[0][lk + 1][lr] = vw.y;
    Ws[0][lk + 2][lr] = vw.z; Ws[0][lk + 3][lr] = vw.w;
    __syncthreads();

    int cur = 0;
    for (int it = 0; it < nk; it++) {
        float4 vaN = Z, vwN = Z;
        if (it + 1 < nk) {
            if (aok) vaN = *(const float4*)(ap + (it + 1) * 8);
            if (wok) vwN = *(const float4*)(wp + (it + 1) * 8);
        }
#pragma unroll
        for (int k = 0; k < 8; k++) {
            float4 a0 = *(const float4*)&As[cur][k][ty * 4];
            float4 a1 = *(const float4*)&As[cur][k][64 + ty * 4];
            float4 w0 = *(const float4*)&Ws[cur][k][tx * 4];
            float4 w1 = *(const float4*)&Ws[cur][k][64 + tx * 4];
            ull W0 = pk2(w0.x, w0.y), W1 = pk2(w0.z, w0.w);
            ull W2 = pk2(w1.x, w1.y), W3 = pk2(w1.z, w1.w);
            float ar[8] = {a0.x, a0.y, a0.z, a0.w, a1.x, a1.y, a1.z, a1.w};
#pragma unroll
            for (int r = 0; r < 8; r++) {
                ull ad = pk2(ar[r], ar[r]);
                fma2(acc[r][0], ad, W0);
                fma2(acc[r][1], ad, W1);
                fma2(acc[r][2], ad, W2);
                fma2(acc[r][3], ad, W3);
            }
        }
        if (it + 1 < nk) {
            int nxt = cur ^ 1;
            As[nxt][lk + 0][lr] = vaN.x; As[nxt][lk + 1][lr] = vaN.y;
            As[nxt][lk + 2][lr] = vaN.z; As[nxt][lk + 3][lr] = vaN.w;
            Ws[nxt][lk + 0][lr] = vwN.x; Ws[nxt][lk + 1][lr] = vwN.y;
            Ws[nxt][lk + 2][lr] = vwN.z; Ws[nxt][lk + 3][lr] = vwN.w;
        }
        __syncthreads();
        cur ^= 1;
    }

    // epilogue
    float* C = (mode == 0) ? g_locC : (mode == 1) ? g_userC
             : (mode == 2) ? g_hourC : (mode == 3) ? g_wdC : out;
#pragma unroll
    for (int hm = 0; hm < 2; hm++) {
#pragma unroll
        for (int i = 0; i < 4; i++) {
            int row = m0 + hm * 64 + ty * 4 + i;
            if (row >= M) continue;
            int ri = hm * 4 + i;
#pragma unroll
            for (int hn = 0; hn < 2; hn++) {
                int nb = n0 + hn * 64 + tx * 4;
                float2 p0 = upk(acc[ri][hn * 2 + 0]);
                float2 p1 = upk(acc[ri][hn * 2 + 1]);
                float4 v = make_float4(p0.x, p0.y, p1.x, p1.y);
                if (mode < 4) {
                    if (mode == 0) {
                        float4 bv = *(const float4*)&g_biasr[nb];
                        v.x += bv.x; v.y += bv.y; v.z += bv.z; v.w += bv.w;
                    }
                    *(float4*)&C[(size_t)row * NG + nb] = v;
                } else {
                    if (nb < N) {
                        float4 b2 = *(const float4*)&bias2[nb];
                        float mm = g_mix[row];
                        float om = 1.0f - mm;
                        float base = mm * NEGV;
                        float4 o;
                        o.x = base + om * (v.x + b2.x);
                        o.y = base + om * (v.y + b2.y);
                        o.z = base + om * (v.z + b2.z);
                        o.w = base + om * (v.w + b2.w);
                        *(float4*)&C[(size_t)row * NUM_LOC + nb] = o;
                    }
                }
            }
        }
    }
}

// ---------------- persistent LSTM: 128 blocks, all 256 steps in one launch
// block (bi, ci): batch rows [bi*32, bi*32+32), gate cols [ci*128, ci*128+128)
// W_hh slice resident in SMEM; c state in registers; h through L2 (ldcg/stcg).
__global__ void __launch_bounds__(256, 1)
lstm_persistent(const int* __restrict__ locs, const int* __restrict__ usrs,
                const int* __restrict__ wds, const int* __restrict__ sms) {
    extern __shared__ char smraw[];
    float* ws = (float*)smraw;                     // [256 k][128 cols]
    float2* hs = (float2*)(smraw + 131072);        // [256 k][33 rows] duplicated pairs

    const int tid = threadIdx.x;
    const int bi = blockIdx.x & 15;
    const int ci = blockIdx.x >> 4;
    const int b0 = bi * 32;
    const int n0 = ci * 128;
    const int cell = tid & 31;
    const int bG = tid >> 5;
    const int cellG = ci * 32 + cell;
    const int col = n0 + (cell << 2);

    // stage W slice: ws[k][c] = Whhr[(n0+c)][k]
    for (int i = tid; i < 8192; i += 256) {
        int c = i & 127, kq = (i >> 7) << 2;
        float4 v = *(const float4*)&g_Whhr[(n0 + c) * DD + kq];
        ws[(kq + 0) * 128 + c] = v.x;
        ws[(kq + 1) * 128 + c] = v.y;
        ws[(kq + 2) * 128 + c] = v.z;
        ws[(kq + 3) * 128 + c] = v.w;
    }

    int brow[4], sl[4];
    float cst[4];
    float4 G[4];
#pragma unroll
    for (int j = 0; j < 4; j++) {
        brow[j] = b0 + bG * 4 + j;
        sl[j] = g_seqlen[brow[j]];
        cst[j] = 0.0f;
    }
    // gather t = 0 (bias folded into locC)
#pragma unroll
    for (int j = 0; j < 4; j++) {
        int b = brow[j];
        int li = __ldg(&locs[b * SS]);
        int ui = __ldg(&usrs[b * SS]);
        int wi = __ldg(&wds[b * SS]);
        int hr = __ldg(&sms[b * SS]) / 60;
        float4 v1 = *(const float4*)&g_locC[(size_t)li * NG + col];
        float4 v2 = *(const float4*)&g_userC[(size_t)ui * NG + col];
        float4 v3 = *(const float4*)&g_hourC[hr * NG + col];
        float4 v4 = *(const float4*)&g_wdC[wi * NG + col];
        G[j].x = v1.x + v2.x + v3.x + v4.x;
        G[j].y = v1.y + v2.y + v3.y + v4.y;
        G[j].z = v1.z + v2.z + v3.z + v4.z;
        G[j].w = v1.w + v2.w + v3.w + v4.w;
    }
    __syncthreads();   // ws ready

    const int hr_ld = tid >> 3;
    const int hk_ld = (tid & 7) << 2;

    for (int t = 0; t < SS; t++) {
        ull acc01[4], acc23[4];
#pragma unroll
        for (int j = 0; j < 4; j++) {
            acc01[j] = pk2(G[j].x, G[j].y);
            acc23[j] = pk2(G[j].z, G[j].w);
        }
        if (t > 0) {
            if (tid == 0) {
                volatile int* p = &g_bar[(t - 1) * 16 + bi];
                while (*p < 8) {}
                __threadfence();
            }
            __syncthreads();
            const float* h_in = g_h[t & 1];
            const float* hp = h_in + (b0 + hr_ld) * DD + hk_ld;
#pragma unroll
            for (int q = 0; q < 8; q++) {
                float4 v = __ldcg((const float4*)(hp + q * 32));
                int k = hk_ld + q * 32;
                hs[(k + 0) * 33 + hr_ld] = make_float2(v.x, v.x);
                hs[(k + 1) * 33 + hr_ld] = make_float2(v.y, v.y);
                hs[(k + 2) * 33 + hr_ld] = make_float2(v.z, v.z);
                hs[(k + 3) * 33 + hr_ld] = make_float2(v.w, v.w);
            }
            __syncthreads();
#pragma unroll 8
            for (int k = 0; k < DD; k++) {
                float4 w4 = *(const float4*)&ws[(k << 7) + (cell << 2)];
                ull W01 = pk2(w4.x, w4.y);
                ull W23 = pk2(w4.z, w4.w);
                const ull* hp2 = (const ull*)&hs[k * 33 + bG * 4];
#pragma unroll
                for (int j = 0; j < 4; j++) {
                    ull hb = hp2[j];
                    fma2(acc01[j], hb, W01);
                    fma2(acc23[j], hb, W23);
                }
            }
        }
        float* h_out = g_h[(t + 1) & 1];
#pragma unroll
        for (int j = 0; j < 4; j++) {
            float2 a01 = upk(acc01[j]);
            float2 a23 = upk(acc23[j]);
            float ii = a01.x, ff = a01.y, gg = a23.x, oo = a23.y;
            float cn = sigm(ff) * cst[j] + sigm(ii) * tanh_(gg);
            float hn = sigm(oo) * tanh_(cn);
            cst[j] = cn;
            __stcg(&h_out[brow[j] * DD + cellG], hn);
            if (t == sl[j]) g_context[brow[j] * DD + cellG] = hn;
        }
        __threadfence();
        __syncthreads();
        if (tid == 0) atomicAdd(&g_bar[t * 16 + bi], 1);
        if (t < SS - 1) {
            int tn = t + 1;
#pragma unroll
            for (int j = 0; j < 4; j++) {
                int b = brow[j];
                int li = __ldg(&locs[b * SS + tn]);
                int ui = __ldg(&usrs[b * SS + tn]);
                int wi = __ldg(&wds[b * SS + tn]);
                int hr = __ldg(&sms[b * SS + tn]) / 60;
                float4 v1 = *(const float4*)&g_locC[(size_t)li * NG + col];
                float4 v2 = *(const float4*)&g_userC[(size_t)ui * NG + col];
                float4 v3 = *(const float4*)&g_hourC[hr * NG + col];
                float4 v4 = *(const float4*)&g_wdC[wi * NG + col];
                G[j].x = v1.x + v2.x + v3.x + v4.x;
                G[j].y = v1.y + v2.y + v3.y + v4.y;
                G[j].z = v1.z + v2.z + v3.z + v4.z;
                G[j].w = v1.w + v2.w + v3.w + v4.w;
            }
        }
    }
}

// ---------------- context MLP: hidden1 = gelu(ctx @ np_W1^T + b1); mix ------
__global__ void ctx_mlp(const float* __restrict__ np_W1, const float* __restrict__ np_b1,
                        const float* __restrict__ mx_W, const float* __restrict__ mx_b) {
    int b = blockIdx.x, tid = threadIdx.x;
    __shared__ float ctx[DD];
    __shared__ float red[DD];
    ctx[tid] = g_context[b * DD + tid];
    __syncthreads();
    float accv = np_b1[tid];
    const float* w = np_W1 + (size_t)tid * DD;
#pragma unroll 4
    for (int k = 0; k < DD; k++) accv += ctx[k] * w[k];
    g_hidden1[b * DD + tid] = geluf(accv);

    red[tid] = ctx[tid] * mx_W[tid];
    __syncthreads();
    for (int off = 128; off > 0; off >>= 1) {
        if (tid < off) red[tid] += red[tid + off];
        __syncthreads();
    }
    if (tid == 0) g_mix[b] = 1.0f / (1.0f + expf(-(red[0] + mx_b[0]))) * 0.9f + 0.05f;
}

// ---------------- recent-location scoring + dedup ----------------
__global__ void recent_kernel(const int* __restrict__ locations,
                              const int* __restrict__ start_mins,
                              const float* __restrict__ loc_table,
                              const float* __restrict__ sc_W1,
                              const float* __restrict__ sc_b1,
                              const float* __restrict__ sc_W2,
                              const float* __restrict__ sc_b2) {
    int b = blockIdx.x, tid = threadIdx.x;   // 128 threads
    __shared__ int rloc[5];
    __shared__ float td[5];
    __shared__ int val[5];
    __shared__ float hid[5][128];
    if (tid < 5) {
        int sl = g_seqlen[b];
        int idx = sl - tid;
        val[tid] = (idx >= 0);
        int ic = idx < 0 ? 0 : idx;
        rloc[tid] = locations[b * SS + ic];
        int ct = start_mins[b * SS + sl];
        td[tid] = (float)(ct - start_mins[b * SS + ic]) / 1440.0f;
    }
    __syncthreads();
    for (int j = 0; j < 5; j++) {
        const float* lt = loc_table + (size_t)rloc[j] * DD;
        const float* w = sc_W1 + (size_t)tid * 258;
        float a = sc_b1[tid] + td[j] * w[256] + (float)j * w[257];
#pragma unroll 4
        for (int k = 0; k < DD; k++) a += lt[k] * w[k];
        hid[j][tid] = geluf(a);
    }
    __syncthreads();
    if (tid < 5) {
        float sc = sc_b2[0];
        for (int k = 0; k < 128; k++) sc += hid[tid][k] * sc_W2[k];
        int keep = val[tid];
        for (int jp = 0; jp < tid; jp++)
            if (val[jp] && rloc[jp] == rloc[tid]) keep = 0;
        g_recloc[b * 5 + tid] = keep ? rloc[tid] : -1;
        g_recscore[b * 5 + tid] = sc;
    }
}

// ---------------- fixup: overwrite kept recent locations ----------------
__global__ void fixup_kernel(const float* __restrict__ np_W2,
                             const float* __restrict__ np_b2,
                             float* __restrict__ out) {
    int b = blockIdx.x, tid = threadIdx.x;   // 256 threads
    __shared__ float h1[DD];
    __shared__ float red[DD];
    h1[tid] = g_hidden1[b * DD + tid];
    __syncthreads();
    float mm = g_mix[b];
    for (int j = 0; j < 5; j++) {
        int l = g_recloc[b * 5 + j];
        if (l < 0) continue;
        red[tid] = h1[tid] * np_W2[(size_t)l * DD + tid];
        __syncthreads();
        for (int off = 128; off > 0; off >>= 1) {
            if (tid < off) red[tid] += red[tid + off];
            __syncthreads();
        }
        if (tid == 0)
            out[(size_t)b * NUM_LOC + l] =
                mm * g_recscore[b * 5 + j] + (1.0f - mm) * (red[0] + np_b2[l]);
        __syncthreads();
    }
}

// ---------------- launch ----------------
extern "C" void kernel_launch(void* const* d_in, const int* in_sizes, int n_in,
                              void* d_out, int out_size) {
    const int* locations   = (const int*)d_in[0];
    const int* users       = (const int*)d_in[1];
    const int* weekdays    = (const int*)d_in[2];
    const int* start_mins  = (const int*)d_in[3];
    const void* mask       = d_in[4];
    const float* loc_table  = (const float*)d_in[5];
    const float* user_table = (const float*)d_in[6];
    const float* hour_table = (const float*)d_in[7];
    const float* wd_table   = (const float*)d_in[8];
    const float* W_ih = (const float*)d_in[9];
    const float* W_hh = (const float*)d_in[10];
    const float* b_ih = (const float*)d_in[11];
    const float* b_hh = (const float*)d_in[12];
    const float* sc_W1 = (const float*)d_in[13];
    const float* sc_b1 = (const float*)d_in[14];
    const float* sc_W2 = (const float*)d_in[15];
    const float* sc_b2 = (const float*)d_in[16];
    const float* np_W1 = (const float*)d_in[17];
    const float* np_b1 = (const float*)d_in[18];
    const float* np_W2 = (const float*)d_in[19];
    const float* np_b2 = (const float*)d_in[20];
    const float* mx_W = (const float*)d_in[21];
    const float* mx_b = (const float*)d_in[22];
    float* out = (float*)d_out;

    detect_mask<<<1, 256>>>((const unsigned char*)mask);
    seqlen_kernel<<<2, 256>>>(mask);
    reorder_kernel<<<1024, 256>>>(W_hh, b_ih, b_hh);

    gemm128<<<dim3(391, 8), 256>>>(loc_table, NUM_LOC, 256, W_ih, 448, 0, 256, NG, 0, nullptr, nullptr);
    gemm128<<<dim3(79, 8), 256>>>(user_table, NUM_USERS, 64, W_ih, 448, 256, 64, NG, 1, nullptr, nullptr);
    gemm128<<<dim3(1, 8), 256>>>(hour_table, 25, 64, W_ih, 448, 320, 64, NG, 2, nullptr, nullptr);
    gemm128<<<dim3(1, 8), 256>>>(wd_table, 8, 64, W_ih, 448, 384, 64, NG, 3, nullptr, nullptr);

    cudaFuncSetAttribute(lstm_persistent, cudaFuncAttributeMaxDynamicSharedMemorySize, 198656);
    lstm_persistent<<<128, 256, 198656>>>(locations, users, weekdays, start_mins);

    ctx_mlp<<<512, 256>>>(np_W1, np_b1, mx_W, mx_b);
    recent_kernel<<<512, 128>>>(locations, start_mins, loc_table,
                                sc_W1, sc_b1, sc_W2, sc_b2);
    gemm128<<<dim3(4, 391), 256>>>(nullptr, BB, 256, np_W2, 256, 0, 256, NUM_LOC, 4, np_b2, out);
    fixup_kernel<<<512, 256>>>(np_W2, np_b2, out);
}